// round 1
// baseline (speedup 1.0000x reference)
#include <cuda_runtime.h>
#include <math.h>

#define D_MODEL 1024
#define HIDDEN  4096
#define NEXP    8
#define NSH     2
#define NTOK    4096          // 2 * 2048 tokens
#define CAP     4096          // per-expert slot capacity (worst case = all tokens)
#define NZ      (NEXP + NSH)  // grouped-GEMM z dimension: 8 routed + 2 shared

// ---------------- device scratch (static: no allocation at runtime) ----------------
__device__ int   g_cnt[NEXP];
__device__ int   g_slot_tok[NEXP][CAP];
__device__ float g_slot_w[NEXP][CAP];
__device__ int   g_tok_e[NTOK][2];
__device__ float g_tok_w[NTOK][2];
__device__ float g_hr[NEXP][CAP][HIDDEN];   // routed hidden activations (512 MB)
__device__ float g_hs[NSH][NTOK][HIDDEN];   // shared-expert hidden activations (128 MB)

__device__ __forceinline__ float gelu_exact(float v) {
    // torch nn.GELU default (erf variant)
    return 0.5f * v * (1.0f + erff(v * 0.70710678118654752440f));
}

// ---------------- kernel 0: reset per-expert counters ----------------
__global__ void zero_counts_kernel() {
    if (threadIdx.x < NEXP) g_cnt[threadIdx.x] = 0;
}

// ---------------- kernel 1: router (gates -> top2 -> softmax -> scatter) ----------------
__global__ void router_kernel(const float* __restrict__ x,
                              const float* __restrict__ rW,
                              const float* __restrict__ rb) {
    const int t   = blockIdx.x;
    const int tid = threadIdx.x;   // 128 threads
    __shared__ float sg[128][NEXP];

    float acc[NEXP];
    #pragma unroll
    for (int e = 0; e < NEXP; e++) acc[e] = 0.0f;

    const float* xr = x + (size_t)t * D_MODEL;
    for (int d = tid; d < D_MODEL; d += 128) {
        const float xv = xr[d];
        const float* r = rW + (size_t)d * NEXP;
        #pragma unroll
        for (int e = 0; e < NEXP; e++) acc[e] += xv * r[e];
    }
    #pragma unroll
    for (int e = 0; e < NEXP; e++) sg[tid][e] = acc[e];
    __syncthreads();

    if (tid < NEXP) {
        float s = rb[tid];
        for (int i = 0; i < 128; i++) s += sg[i][tid];
        sg[0][tid] = s;
    }
    __syncthreads();

    if (tid == 0) {
        float g[NEXP];
        #pragma unroll
        for (int e = 0; e < NEXP; e++) g[e] = sg[0][e];

        // top-2 (strict > matches jax top_k tie-break: lowest index first)
        int e0 = 0;
        #pragma unroll
        for (int e = 1; e < NEXP; e++) if (g[e] > g[e0]) e0 = e;
        int e1 = (e0 == 0) ? 1 : 0;
        #pragma unroll
        for (int e = 0; e < NEXP; e++) if (e != e0 && g[e] > g[e1]) e1 = e;

        // softmax over the two selected logits (stable: g[e0] >= g[e1])
        const float p1  = expf(g[e1] - g[e0]);
        const float inv = 1.0f / (1.0f + p1);
        const float w0  = inv, w1 = p1 * inv;

        g_tok_e[t][0] = e0; g_tok_e[t][1] = e1;
        g_tok_w[t][0] = w0; g_tok_w[t][1] = w1;

        int p = atomicAdd(&g_cnt[e0], 1);
        g_slot_tok[e0][p] = t; g_slot_w[e0][p] = w0;
        p = atomicAdd(&g_cnt[e1], 1);
        g_slot_tok[e1][p] = t; g_slot_w[e1][p] = w1;
    }
}

// ---------------- kernel 2: initialize output with all bias terms ----------------
__global__ void init_out_kernel(float* __restrict__ out,
                                const float* __restrict__ b2,
                                const float* __restrict__ sb2) {
    const int idx = blockIdx.x * 256 + threadIdx.x;
    if (idx >= NTOK * D_MODEL) return;
    const int t = idx >> 10;     // / D_MODEL
    const int d = idx & 1023;    // % D_MODEL
    float v = 0.5f * (sb2[d] + sb2[D_MODEL + d]);
    v += g_tok_w[t][0] * b2[(size_t)g_tok_e[t][0] * D_MODEL + d];
    v += g_tok_w[t][1] * b2[(size_t)g_tok_e[t][1] * D_MODEL + d];
    out[idx] = v;
}

// ---------------- kernel 3: grouped GEMM1 + bias + GELU ----------------
// C[m, n] = gelu( A[m,:] @ B[:, n] + bias[n] ),  A rows gathered (routed) or dense (shared)
// BM=128, BN=64, BK=16, 256 threads, 8x4 register micro-tile per thread.
__global__ __launch_bounds__(256) void gemm1_kernel(
    const float* __restrict__ x,
    const float* __restrict__ W1, const float* __restrict__ b1,
    const float* __restrict__ sW1, const float* __restrict__ sb1)
{
    const int z   = blockIdx.z;
    const int m0  = blockIdx.x * 128;
    const int n0  = blockIdx.y * 64;
    const int tid = threadIdx.x;

    int cnt;
    const float* Bmat;
    const float* bias;
    float* hout;
    const int* toks = nullptr;
    if (z < NEXP) {
        cnt = g_cnt[z];
        if (m0 >= cnt) return;                       // empty tile: early exit
        Bmat = W1 + (size_t)z * D_MODEL * HIDDEN;
        bias = b1 + (size_t)z * HIDDEN;
        hout = &g_hr[z][0][0];
        toks = g_slot_tok[z];
    } else {
        const int s = z - NEXP;
        cnt  = NTOK;
        Bmat = sW1 + (size_t)s * D_MODEL * HIDDEN;
        bias = sb1 + (size_t)s * HIDDEN;
        hout = &g_hs[s][0][0];
    }

    __shared__ float As[16][128];   // K-major, M contiguous (for vector LDS)
    __shared__ float Bs[16][64];

    // A loading plan: 128 rows x 16 k = 512 float4 -> 2 per thread
    const int rowA0 = tid >> 2,         k40 = tid & 3;
    const int rowA1 = (tid + 256) >> 2, k41 = (tid + 256) & 3;
    const int r0 = m0 + rowA0, r1 = m0 + rowA1;
    const float* aptr0 = nullptr;
    const float* aptr1 = nullptr;
    if (toks) {
        if (r0 < cnt) aptr0 = x + (size_t)toks[r0] * D_MODEL;
        if (r1 < cnt) aptr1 = x + (size_t)toks[r1] * D_MODEL;
    } else {
        aptr0 = x + (size_t)r0 * D_MODEL;
        aptr1 = x + (size_t)r1 * D_MODEL;
    }
    // B loading plan: 16 k x 64 n = 256 float4 -> 1 per thread
    const int kB = tid >> 4, n4 = tid & 15;

    const int tx = tid & 15, ty = tid >> 4;   // output: rows ty*8.., cols tx*4..
    float acc[8][4];
    #pragma unroll
    for (int i = 0; i < 8; i++)
        #pragma unroll
        for (int j = 0; j < 4; j++) acc[i][j] = 0.0f;

    for (int k0 = 0; k0 < D_MODEL; k0 += 16) {
        float4 a0 = make_float4(0.f,0.f,0.f,0.f);
        float4 a1 = make_float4(0.f,0.f,0.f,0.f);
        if (aptr0) a0 = *(const float4*)(aptr0 + k0 + k40 * 4);
        if (aptr1) a1 = *(const float4*)(aptr1 + k0 + k41 * 4);
        const float4 bv = *(const float4*)(Bmat + (size_t)(k0 + kB) * HIDDEN + n0 + n4 * 4);

        As[k40*4+0][rowA0] = a0.x;
        As[k40*4+1][rowA0] = a0.y;
        As[k40*4+2][rowA0] = a0.z;
        As[k40*4+3][rowA0] = a0.w;
        As[k41*4+0][rowA1] = a1.x;
        As[k41*4+1][rowA1] = a1.y;
        As[k41*4+2][rowA1] = a1.z;
        As[k41*4+3][rowA1] = a1.w;
        *(float4*)&Bs[kB][n4*4] = bv;
        __syncthreads();

        #pragma unroll
        for (int k = 0; k < 16; k++) {
            const float4 av0 = *(const float4*)&As[k][ty*8];
            const float4 av1 = *(const float4*)&As[k][ty*8 + 4];
            const float4 b   = *(const float4*)&Bs[k][tx*4];
            const float a[8]  = {av0.x, av0.y, av0.z, av0.w, av1.x, av1.y, av1.z, av1.w};
            const float bb[4] = {b.x, b.y, b.z, b.w};
            #pragma unroll
            for (int i = 0; i < 8; i++)
                #pragma unroll
                for (int j = 0; j < 4; j++)
                    acc[i][j] += a[i] * bb[j];
        }
        __syncthreads();
    }

    const float4 biasv = *(const float4*)(bias + n0 + tx * 4);
    #pragma unroll
    for (int i = 0; i < 8; i++) {
        const int m = m0 + ty * 8 + i;
        if (m >= cnt) continue;
        float4 o;
        o.x = gelu_exact(acc[i][0] + biasv.x);
        o.y = gelu_exact(acc[i][1] + biasv.y);
        o.z = gelu_exact(acc[i][2] + biasv.z);
        o.w = gelu_exact(acc[i][3] + biasv.w);
        *(float4*)(hout + (size_t)m * HIDDEN + n0 + tx * 4) = o;
    }
}

// ---------------- kernel 4: grouped GEMM2 + weighted scatter-add ----------------
// out[token, n] += w * ( h[m,:] @ B[:, n] )   (biases already in init_out)
__global__ __launch_bounds__(256) void gemm2_kernel(
    const float* __restrict__ W2,
    const float* __restrict__ sW2,
    float* __restrict__ out)
{
    const int z   = blockIdx.z;
    const int m0  = blockIdx.x * 128;
    const int n0  = blockIdx.y * 64;
    const int tid = threadIdx.x;

    int cnt;
    const float* Amat;
    const float* Bmat;
    const int*   toks = nullptr;
    const float* ws   = nullptr;
    if (z < NEXP) {
        cnt = g_cnt[z];
        if (m0 >= cnt) return;
        Amat = &g_hr[z][0][0];
        Bmat = W2 + (size_t)z * HIDDEN * D_MODEL;
        toks = g_slot_tok[z];
        ws   = g_slot_w[z];
    } else {
        const int s = z - NEXP;
        cnt  = NTOK;
        Amat = &g_hs[s][0][0];
        Bmat = sW2 + (size_t)s * HIDDEN * D_MODEL;
    }

    __shared__ float As[16][128];
    __shared__ float Bs[16][64];

    const int rowA0 = tid >> 2,         k40 = tid & 3;
    const int rowA1 = (tid + 256) >> 2, k41 = (tid + 256) & 3;
    const int r0 = m0 + rowA0, r1 = m0 + rowA1;
    const float* aptr0 = (r0 < cnt) ? (Amat + (size_t)r0 * HIDDEN) : nullptr;
    const float* aptr1 = (r1 < cnt) ? (Amat + (size_t)r1 * HIDDEN) : nullptr;
    const int kB = tid >> 4, n4 = tid & 15;

    const int tx = tid & 15, ty = tid >> 4;
    float acc[8][4];
    #pragma unroll
    for (int i = 0; i < 8; i++)
        #pragma unroll
        for (int j = 0; j < 4; j++) acc[i][j] = 0.0f;

    for (int k0 = 0; k0 < HIDDEN; k0 += 16) {
        float4 a0 = make_float4(0.f,0.f,0.f,0.f);
        float4 a1 = make_float4(0.f,0.f,0.f,0.f);
        if (aptr0) a0 = *(const float4*)(aptr0 + k0 + k40 * 4);
        if (aptr1) a1 = *(const float4*)(aptr1 + k0 + k41 * 4);
        const float4 bv = *(const float4*)(Bmat + (size_t)(k0 + kB) * D_MODEL + n0 + n4 * 4);

        As[k40*4+0][rowA0] = a0.x;
        As[k40*4+1][rowA0] = a0.y;
        As[k40*4+2][rowA0] = a0.z;
        As[k40*4+3][rowA0] = a0.w;
        As[k41*4+0][rowA1] = a1.x;
        As[k41*4+1][rowA1] = a1.y;
        As[k41*4+2][rowA1] = a1.z;
        As[k41*4+3][rowA1] = a1.w;
        *(float4*)&Bs[kB][n4*4] = bv;
        __syncthreads();

        #pragma unroll
        for (int k = 0; k < 16; k++) {
            const float4 av0 = *(const float4*)&As[k][ty*8];
            const float4 av1 = *(const float4*)&As[k][ty*8 + 4];
            const float4 b   = *(const float4*)&Bs[k][tx*4];
            const float a[8]  = {av0.x, av0.y, av0.z, av0.w, av1.x, av1.y, av1.z, av1.w};
            const float bb[4] = {b.x, b.y, b.z, b.w};
            #pragma unroll
            for (int i = 0; i < 8; i++)
                #pragma unroll
                for (int j = 0; j < 4; j++)
                    acc[i][j] += a[i] * bb[j];
        }
        __syncthreads();
    }

    #pragma unroll
    for (int i = 0; i < 8; i++) {
        const int m = m0 + ty * 8 + i;
        if (m >= cnt) continue;
        if (toks) {
            const int   t = toks[m];
            const float w = ws[m];
            float* op = out + (size_t)t * D_MODEL + n0 + tx * 4;
            atomicAdd(op + 0, w * acc[i][0]);
            atomicAdd(op + 1, w * acc[i][1]);
            atomicAdd(op + 2, w * acc[i][2]);
            atomicAdd(op + 3, w * acc[i][3]);
        } else {
            float* op = out + (size_t)m * D_MODEL + n0 + tx * 4;
            atomicAdd(op + 0, 0.5f * acc[i][0]);
            atomicAdd(op + 1, 0.5f * acc[i][1]);
            atomicAdd(op + 2, 0.5f * acc[i][2]);
            atomicAdd(op + 3, 0.5f * acc[i][3]);
        }
    }
}

// ---------------- launch ----------------
extern "C" void kernel_launch(void* const* d_in, const int* in_sizes, int n_in,
                              void* d_out, int out_size) {
    (void)in_sizes; (void)n_in; (void)out_size;
    const float* x   = (const float*)d_in[0];
    const float* rW  = (const float*)d_in[1];
    const float* rb  = (const float*)d_in[2];
    const float* W1  = (const float*)d_in[3];
    const float* b1  = (const float*)d_in[4];
    const float* W2  = (const float*)d_in[5];
    const float* b2  = (const float*)d_in[6];
    const float* sW1 = (const float*)d_in[7];
    const float* sb1 = (const float*)d_in[8];
    const float* sW2 = (const float*)d_in[9];
    const float* sb2 = (const float*)d_in[10];
    float* out = (float*)d_out;

    zero_counts_kernel<<<1, 32>>>();
    router_kernel<<<NTOK, 128>>>(x, rW, rb);
    init_out_kernel<<<(NTOK * D_MODEL) / 256, 256>>>(out, b2, sb2);
    gemm1_kernel<<<dim3(CAP / 128, HIDDEN / 64, NZ), 256>>>(x, W1, b1, sW1, sb1);
    gemm2_kernel<<<dim3(CAP / 128, D_MODEL / 64, NZ), 256>>>(W2, sW2, out);
}

// round 4
// speedup vs baseline: 2.6851x; 2.6851x over previous
#include <cuda_runtime.h>
#include <cstdint>
#include <math.h>

#define D_MODEL 1024
#define HIDDEN  4096
#define NEXP    8
#define NSH     2
#define NTOK    4096
#define CAP     4096
#define NZ      (NEXP + NSH)
#define NSLOT   16384

// ---------------- device scratch (static; zero runtime allocation) ----------------
__device__ int   g_cnt[NEXP];
__device__ int   g_slot_tok[NEXP][CAP];
__device__ float g_slot_w[NEXP][CAP];
__device__ int   g_tok_e[NTOK][2];
__device__ float g_tok_w[NTOK][2];
__device__ int   g_grp_base[NZ];
__device__ int   g_grp_cnt[NZ];
__device__ __align__(16) float g_h[(size_t)NSLOT * HIDDEN];   // tf32-rounded hidden acts

__device__ __forceinline__ float gelu_exact(float v) {
    return 0.5f * v * (1.0f + erff(v * 0.70710678118654752440f));
}
__device__ __forceinline__ float tf32r(float f) {
    uint32_t u;
    asm("cvt.rna.tf32.f32 %0, %1;" : "=r"(u) : "f"(f));
    return __uint_as_float(u);
}
__device__ __forceinline__ float4 tf32r4(float4 v) {
    return make_float4(tf32r(v.x), tf32r(v.y), tf32r(v.z), tf32r(v.w));
}
__device__ __forceinline__ void mma_tf32(float* d, const uint32_t* a, const uint32_t* b) {
    asm volatile(
        "mma.sync.aligned.m16n8k8.row.col.f32.tf32.tf32.f32 "
        "{%0,%1,%2,%3}, {%4,%5,%6,%7}, {%8,%9}, {%0,%1,%2,%3};"
        : "+f"(d[0]), "+f"(d[1]), "+f"(d[2]), "+f"(d[3])
        : "r"(a[0]), "r"(a[1]), "r"(a[2]), "r"(a[3]), "r"(b[0]), "r"(b[1]));
}

// ---------------- small kernels (R1-proven) ----------------
__global__ void zero_counts_kernel() {
    if (threadIdx.x < NEXP) g_cnt[threadIdx.x] = 0;
}

__global__ void router_kernel(const float* __restrict__ x,
                              const float* __restrict__ rW,
                              const float* __restrict__ rb) {
    const int t = blockIdx.x, tid = threadIdx.x;
    __shared__ float sg[128][NEXP];
    float acc[NEXP];
    #pragma unroll
    for (int e = 0; e < NEXP; e++) acc[e] = 0.0f;
    const float* xr = x + (size_t)t * D_MODEL;
    for (int d = tid; d < D_MODEL; d += 128) {
        const float xv = xr[d];
        const float* r = rW + (size_t)d * NEXP;
        #pragma unroll
        for (int e = 0; e < NEXP; e++) acc[e] += xv * r[e];
    }
    #pragma unroll
    for (int e = 0; e < NEXP; e++) sg[tid][e] = acc[e];
    __syncthreads();
    if (tid < NEXP) {
        float s = rb[tid];
        for (int i = 0; i < 128; i++) s += sg[i][tid];
        sg[0][tid] = s;
    }
    __syncthreads();
    if (tid == 0) {
        float g[NEXP];
        #pragma unroll
        for (int e = 0; e < NEXP; e++) g[e] = sg[0][e];
        int e0 = 0;
        #pragma unroll
        for (int e = 1; e < NEXP; e++) if (g[e] > g[e0]) e0 = e;
        int e1 = (e0 == 0) ? 1 : 0;
        #pragma unroll
        for (int e = 0; e < NEXP; e++) if (e != e0 && g[e] > g[e1]) e1 = e;
        const float p1 = expf(g[e1] - g[e0]);
        const float inv = 1.0f / (1.0f + p1);
        const float w0 = inv, w1 = p1 * inv;
        g_tok_e[t][0] = e0; g_tok_e[t][1] = e1;
        g_tok_w[t][0] = w0; g_tok_w[t][1] = w1;
        int p = atomicAdd(&g_cnt[e0], 1);
        g_slot_tok[e0][p] = t; g_slot_w[e0][p] = w0;
        p = atomicAdd(&g_cnt[e1], 1);
        g_slot_tok[e1][p] = t; g_slot_w[e1][p] = w1;
    }
}

__global__ void offsets_kernel() {
    if (threadIdx.x == 0) {
        int acc = 0;
        for (int e = 0; e < NEXP; e++) { g_grp_base[e] = acc; g_grp_cnt[e] = g_cnt[e]; acc += g_cnt[e]; }
        for (int s = 0; s < NSH; s++)  { g_grp_base[NEXP + s] = 8192 + s * NTOK; g_grp_cnt[NEXP + s] = NTOK; }
    }
}

__global__ void init_out_kernel(float* __restrict__ out,
                                const float* __restrict__ b2,
                                const float* __restrict__ sb2) {
    const int idx = blockIdx.x * 256 + threadIdx.x;
    if (idx >= NTOK * D_MODEL) return;
    const int t = idx >> 10, d = idx & 1023;
    float v = 0.5f * (sb2[d] + sb2[D_MODEL + d]);
    v += g_tok_w[t][0] * b2[(size_t)g_tok_e[t][0] * D_MODEL + d];
    v += g_tok_w[t][1] * b2[(size_t)g_tok_e[t][1] * D_MODEL + d];
    out[idx] = v;
}

// ---------------- tf32 mma.sync grouped GEMM ----------------
// CTA 128x128, BK=16, 8 warps (warp tile 64x32), static-smem double buffer,
// register prefetch of next chunk overlapped with MMA.
#define BM 128
#define BN 128
#define BK 16
#define A_LD 20
#define B_LD 136

template<int KTOT, bool G1>
__global__ __launch_bounds__(256, 2) void moe_mma(
    const float* __restrict__ xin,      // G1: x (fp32); G2: unused
    const float* __restrict__ Wr,       // routed weights base [NEXP][K][N]
    const float* __restrict__ Wsh,      // shared weights base [NSH][K][N]
    const float* __restrict__ bias_r, const float* __restrict__ bias_s,
    float* __restrict__ out)
{
    constexpr int NC  = KTOT / BK;
    constexpr int BLD = G1 ? HIDDEN : D_MODEL;   // global row stride of B
    const int z   = blockIdx.z;
    const int cnt = g_grp_cnt[z];
    const int m0  = blockIdx.x * BM;
    if (m0 >= cnt) return;
    const int n0    = blockIdx.y * BN;
    const int hbase = g_grp_base[z];

    __shared__ float sA[2][BM * A_LD];
    __shared__ float sB[2][BK * B_LD];

    const int tid = threadIdx.x, lane = tid & 31, wid = tid >> 5;
    const int wm = (wid & 1) * 64, wn = (wid >> 1) * 32;
    const int fr = lane >> 2, fc = lane & 3;

    // ---- loader plans ----
    // A: 128 rows x 16 floats = 512 float4; 2 per thread.
    const int ar0 = tid >> 2, ar1 = (tid >> 2) + 64;   // rows
    const int ac  = (tid & 3) * 4;                     // col (float)
    const float* arow0;
    const float* arow1;
    if (G1) {
        int t0, t1;
        if (z < NEXP) {
            const int i0 = m0 + ar0, i1 = m0 + ar1;
            t0 = g_slot_tok[z][i0 < cnt ? i0 : cnt - 1];
            t1 = g_slot_tok[z][i1 < cnt ? i1 : cnt - 1];
        } else {
            t0 = m0 + ar0; t1 = m0 + ar1;
        }
        arow0 = xin + (size_t)t0 * D_MODEL + ac;
        arow1 = xin + (size_t)t1 * D_MODEL + ac;
    } else {
        arow0 = g_h + (size_t)(hbase + m0 + ar0) * HIDDEN + ac;
        arow1 = g_h + (size_t)(hbase + m0 + ar1) * HIDDEN + ac;
    }
    // B: 16 rows x 128 floats = 512 float4; 2 per thread.
    const int br0 = tid >> 5, br1 = (tid >> 5) + 8;    // k-rows within chunk
    const int bc  = (tid & 31) * 4;                    // col (float)
    const float* Bbase = (z < NEXP) ? Wr  + (size_t)z * D_MODEL * HIDDEN
                                    : Wsh + (size_t)(z - NEXP) * D_MODEL * HIDDEN;
    const float* brow = Bbase + n0 + bc;

    float4 pa0, pa1, pb0, pb1;
    auto fetch = [&](int c) {
        const int k = c * BK;
        pa0 = tf32r4(*(const float4*)(arow0 + k));
        pa1 = tf32r4(*(const float4*)(arow1 + k));
        pb0 = tf32r4(*(const float4*)(brow + (size_t)(k + br0) * BLD));
        pb1 = tf32r4(*(const float4*)(brow + (size_t)(k + br1) * BLD));
    };
    auto stage_store = [&](int s) {
        *(float4*)&sA[s][ar0 * A_LD + ac] = pa0;
        *(float4*)&sA[s][ar1 * A_LD + ac] = pa1;
        *(float4*)&sB[s][br0 * B_LD + bc] = pb0;
        *(float4*)&sB[s][br1 * B_LD + bc] = pb1;
    };

    float acc[4][4][4];
    #pragma unroll
    for (int mt = 0; mt < 4; mt++)
        #pragma unroll
        for (int nt = 0; nt < 4; nt++)
            #pragma unroll
            for (int q = 0; q < 4; q++) acc[mt][nt][q] = 0.0f;

    fetch(0);
    stage_store(0);
    __syncthreads();

    #pragma unroll 1
    for (int c = 0; c < NC; c++) {
        const int s = c & 1;
        if (c + 1 < NC) fetch(c + 1);   // global->reg, overlapped with MMA below

        const uint32_t* Au = (const uint32_t*)sA[s];
        const uint32_t* Bu = (const uint32_t*)sB[s];
        #pragma unroll
        for (int kk = 0; kk < 2; kk++) {
            uint32_t a[4][4], b[4][2];
            #pragma unroll
            for (int mt = 0; mt < 4; mt++) {
                const int r0 = wm + mt * 16 + fr;
                a[mt][0] = Au[r0 * A_LD + kk * 8 + fc];
                a[mt][1] = Au[(r0 + 8) * A_LD + kk * 8 + fc];
                a[mt][2] = Au[r0 * A_LD + kk * 8 + fc + 4];
                a[mt][3] = Au[(r0 + 8) * A_LD + kk * 8 + fc + 4];
            }
            #pragma unroll
            for (int nt = 0; nt < 4; nt++) {
                const int cB = wn + nt * 8 + fr;
                b[nt][0] = Bu[(kk * 8 + fc) * B_LD + cB];
                b[nt][1] = Bu[(kk * 8 + fc + 4) * B_LD + cB];
            }
            #pragma unroll
            for (int mt = 0; mt < 4; mt++)
                #pragma unroll
                for (int nt = 0; nt < 4; nt++)
                    mma_tf32(acc[mt][nt], a[mt], b[nt]);
        }

        if (c + 1 < NC) {
            __syncthreads();            // all warps done reading stage s^1 (chunk c-1)
            stage_store(s ^ 1);
            __syncthreads();            // stores visible before compute(c+1)
        }
    }

    // ---------------- epilogue ----------------
    if (G1) {
        const float* bias = (z < NEXP) ? bias_r + (size_t)z * HIDDEN + n0
                                       : bias_s + (size_t)(z - NEXP) * HIDDEN + n0;
        #pragma unroll
        for (int mt = 0; mt < 4; mt++) {
            #pragma unroll
            for (int h2 = 0; h2 < 2; h2++) {
                const int mloc = wm + mt * 16 + fr + 8 * h2;
                if (m0 + mloc < cnt) {
                    float* hrow = g_h + (size_t)(hbase + m0 + mloc) * HIDDEN + n0;
                    #pragma unroll
                    for (int nt = 0; nt < 4; nt++) {
                        const int col = wn + nt * 8 + 2 * fc;
                        float2 o;
                        o.x = tf32r(gelu_exact(acc[mt][nt][2 * h2]     + bias[col]));
                        o.y = tf32r(gelu_exact(acc[mt][nt][2 * h2 + 1] + bias[col + 1]));
                        *(float2*)(hrow + col) = o;
                    }
                }
            }
        }
    } else {
        #pragma unroll
        for (int mt = 0; mt < 4; mt++) {
            #pragma unroll
            for (int h2 = 0; h2 < 2; h2++) {
                const int mloc = wm + mt * 16 + fr + 8 * h2;
                const int m = m0 + mloc;
                if (m < cnt) {
                    int t; float w;
                    if (z < NEXP) { t = g_slot_tok[z][m]; w = g_slot_w[z][m]; }
                    else          { t = m; w = 0.5f; }
                    float* orow = out + (size_t)t * D_MODEL + n0;
                    #pragma unroll
                    for (int nt = 0; nt < 4; nt++) {
                        const int col = wn + nt * 8 + 2 * fc;
                        atomicAdd(orow + col,     w * acc[mt][nt][2 * h2]);
                        atomicAdd(orow + col + 1, w * acc[mt][nt][2 * h2 + 1]);
                    }
                }
            }
        }
    }
}

// ---------------- launch ----------------
extern "C" void kernel_launch(void* const* d_in, const int* in_sizes, int n_in,
                              void* d_out, int out_size) {
    (void)in_sizes; (void)n_in; (void)out_size;
    const float* x   = (const float*)d_in[0];
    const float* rW  = (const float*)d_in[1];
    const float* rb  = (const float*)d_in[2];
    const float* W1  = (const float*)d_in[3];
    const float* b1  = (const float*)d_in[4];
    const float* W2  = (const float*)d_in[5];
    const float* b2  = (const float*)d_in[6];
    const float* sW1 = (const float*)d_in[7];
    const float* sb1 = (const float*)d_in[8];
    const float* sW2 = (const float*)d_in[9];
    const float* sb2 = (const float*)d_in[10];
    float* out = (float*)d_out;

    zero_counts_kernel<<<1, 32>>>();
    router_kernel<<<NTOK, 128>>>(x, rW, rb);
    offsets_kernel<<<1, 32>>>();
    init_out_kernel<<<(NTOK * D_MODEL) / 256, 256>>>(out, b2, sb2);

    moe_mma<D_MODEL, true><<<dim3(CAP / BM, HIDDEN / BN, NZ), 256>>>(
        x, W1, sW1, b1, sb1, nullptr);
    moe_mma<HIDDEN, false><<<dim3(CAP / BM, D_MODEL / BN, NZ), 256>>>(
        nullptr, W2, sW2, nullptr, nullptr, out);
}

// round 8
// speedup vs baseline: 4.2907x; 1.5979x over previous
#include <cuda_runtime.h>
#include <cuda_fp16.h>
#include <cstdint>
#include <math.h>

#define D_MODEL 1024
#define HIDDEN  4096
#define NEXP    8
#define NSH     2
#define NTOK    4096
#define CAP     4096
#define NZ      (NEXP + NSH)
#define NSLOT   16384

// ---------------- device scratch (static; zero runtime allocation) ----------------
__device__ int   g_cnt[NEXP];
__device__ int   g_slot_tok[NEXP][CAP];
__device__ float g_slot_w[NEXP][CAP];
__device__ int   g_tok_e[NTOK][2];
__device__ float g_tok_w[NTOK][2];
__device__ int   g_grp_base[NZ];
__device__ int   g_grp_cnt[NZ];

__device__ __align__(16) __half g_xh[(size_t)NTOK * D_MODEL];            // x fp16
__device__ __align__(16) __half g_w1t[(size_t)NZ * HIDDEN * D_MODEL];    // W1^T fp16 [z][H][D]
__device__ __align__(16) __half g_w2t[(size_t)NZ * D_MODEL * HIDDEN];    // W2^T fp16 [z][D][H]
__device__ __align__(16) __half g_h[(size_t)NSLOT * HIDDEN];             // hidden acts fp16

__device__ __forceinline__ float gelu_exact(float v) {
    return 0.5f * v * (1.0f + erff(v * 0.70710678118654752440f));
}
__device__ __forceinline__ void mma_f16(float* d, const uint32_t* a, const uint32_t* b) {
    asm volatile(
        "mma.sync.aligned.m16n8k16.row.col.f32.f16.f16.f32 "
        "{%0,%1,%2,%3}, {%4,%5,%6,%7}, {%8,%9}, {%0,%1,%2,%3};"
        : "+f"(d[0]), "+f"(d[1]), "+f"(d[2]), "+f"(d[3])
        : "r"(a[0]), "r"(a[1]), "r"(a[2]), "r"(a[3]), "r"(b[0]), "r"(b[1]));
}

// ---------------- small kernels (proven) ----------------
__global__ void zero_counts_kernel() {
    if (threadIdx.x < NEXP) g_cnt[threadIdx.x] = 0;
}

__global__ void router_kernel(const float* __restrict__ x,
                              const float* __restrict__ rW,
                              const float* __restrict__ rb) {
    const int t = blockIdx.x, tid = threadIdx.x;
    __shared__ float sg[128][NEXP];
    float acc[NEXP];
    #pragma unroll
    for (int e = 0; e < NEXP; e++) acc[e] = 0.0f;
    const float* xr = x + (size_t)t * D_MODEL;
    for (int d = tid; d < D_MODEL; d += 128) {
        const float xv = xr[d];
        const float* r = rW + (size_t)d * NEXP;
        #pragma unroll
        for (int e = 0; e < NEXP; e++) acc[e] += xv * r[e];
    }
    #pragma unroll
    for (int e = 0; e < NEXP; e++) sg[tid][e] = acc[e];
    __syncthreads();
    if (tid < NEXP) {
        float s = rb[tid];
        for (int i = 0; i < 128; i++) s += sg[i][tid];
        sg[0][tid] = s;
    }
    __syncthreads();
    if (tid == 0) {
        float g[NEXP];
        #pragma unroll
        for (int e = 0; e < NEXP; e++) g[e] = sg[0][e];
        int e0 = 0;
        #pragma unroll
        for (int e = 1; e < NEXP; e++) if (g[e] > g[e0]) e0 = e;
        int e1 = (e0 == 0) ? 1 : 0;
        #pragma unroll
        for (int e = 0; e < NEXP; e++) if (e != e0 && g[e] > g[e1]) e1 = e;
        const float p1 = expf(g[e1] - g[e0]);
        const float inv = 1.0f / (1.0f + p1);
        const float w0 = inv, w1 = p1 * inv;
        g_tok_e[t][0] = e0; g_tok_e[t][1] = e1;
        g_tok_w[t][0] = w0; g_tok_w[t][1] = w1;
        int p = atomicAdd(&g_cnt[e0], 1);
        g_slot_tok[e0][p] = t; g_slot_w[e0][p] = w0;
        p = atomicAdd(&g_cnt[e1], 1);
        g_slot_tok[e1][p] = t; g_slot_w[e1][p] = w1;
    }
}

__global__ void offsets_kernel() {
    if (threadIdx.x == 0) {
        int acc = 0;
        for (int e = 0; e < NEXP; e++) { g_grp_base[e] = acc; g_grp_cnt[e] = g_cnt[e]; acc += g_cnt[e]; }
        for (int s = 0; s < NSH; s++)  { g_grp_base[NEXP + s] = 8192 + s * NTOK; g_grp_cnt[NEXP + s] = NTOK; }
    }
}

__global__ void init_out_kernel(float* __restrict__ out,
                                const float* __restrict__ b2,
                                const float* __restrict__ sb2) {
    const int idx = blockIdx.x * 256 + threadIdx.x;
    if (idx >= NTOK * D_MODEL) return;
    const int t = idx >> 10, d = idx & 1023;
    float v = 0.5f * (sb2[d] + sb2[D_MODEL + d]);
    v += g_tok_w[t][0] * b2[(size_t)g_tok_e[t][0] * D_MODEL + d];
    v += g_tok_w[t][1] * b2[(size_t)g_tok_e[t][1] * D_MODEL + d];
    out[idx] = v;
}

__global__ void conv_x_kernel(const float* __restrict__ x) {
    const int i = (blockIdx.x * 256 + threadIdx.x) * 4;
    const float4 v = *(const float4*)(x + i);
    *(__half2*)(g_xh + i)     = __floats2half2_rn(v.x, v.y);
    *(__half2*)(g_xh + i + 2) = __floats2half2_rn(v.z, v.w);
}

// [z][R][C] fp32 -> [z][C][R] fp16.  Destination chosen INSIDE device code
// (passing a __device__ global as a kernel argument from host is invalid —
// that was the R3/R5/R6/R7 failure).
__global__ void transp_kernel(const float* __restrict__ srcR, const float* __restrict__ srcS,
                              int which, int R, int C) {
    __half* __restrict__ dst0 = which ? g_w2t : g_w1t;
    const int z = blockIdx.z;
    const float* src = (z < NEXP) ? srcR + (size_t)z * R * C : srcS + (size_t)(z - NEXP) * R * C;
    __half* d = dst0 + (size_t)z * R * C;
    __shared__ float tile[32][33];
    const int c0 = blockIdx.x * 32, r0 = blockIdx.y * 32;
    const int tx = threadIdx.x, ty = threadIdx.y;
    #pragma unroll
    for (int q = 0; q < 4; q++)
        tile[ty + 8 * q][tx] = src[(size_t)(r0 + ty + 8 * q) * C + c0 + tx];
    __syncthreads();
    #pragma unroll
    for (int q = 0; q < 4; q++)
        d[(size_t)(c0 + ty + 8 * q) * R + r0 + tx] = __float2half_rn(tile[tx][ty + 8 * q]);
}

// ---------------- fp16 mma grouped GEMM (R4-proven structure) ----------------
// CTA 128x128, BK=32 halfs, padded linear smem (no swizzle/ldmatrix),
// scalar LDS.32 fragment loads, plain-load double buffer with register prefetch.
#define BM 128
#define BN 128
#define BK 32
#define A_LDH 40                 // halfs per A row (32 + 8 pad) -> 20 u32
#define B_LDH 40
#define A_STG_H (BM * A_LDH)     // 5120 halfs
#define B_STG_H (BN * B_LDH)     // 5120 halfs
#define STAGE_H (A_STG_H + B_STG_H)   // 2 stages = 40 KB

template<int KTOT, bool G1>
__global__ __launch_bounds__(256, 2) void moe_mma(
    const float* __restrict__ bias_r, const float* __restrict__ bias_s,
    float* __restrict__ out)
{
    constexpr int NC = KTOT / BK;
    const int z   = blockIdx.z;
    const int cnt = g_grp_cnt[z];
    const int m0  = blockIdx.x * BM;
    if (m0 >= cnt) return;
    const int n0    = blockIdx.y * BN;
    const int hbase = g_grp_base[z];

    __shared__ __align__(16) __half smbuf[2][STAGE_H];

    const int tid = threadIdx.x, lane = tid & 31, wid = tid >> 5;
    const int wm = (wid & 1) * 64, wn = (wid >> 1) * 32;
    const int fr = lane >> 2, fc = lane & 3;

    // ---- loader plan: thread -> one row (A and B), 32B (2x16B quads) ----
    const int ar = tid >> 1;
    const int q0 = (tid & 1) * 2;
    const __half* asrc;
    if (G1) {
        int tok;
        if (z < NEXP) {
            const int i0 = m0 + ar;
            tok = g_slot_tok[z][i0 < cnt ? i0 : cnt - 1];
        } else tok = m0 + ar;
        asrc = g_xh + (size_t)tok * D_MODEL + q0 * 8;
    } else {
        asrc = g_h + (size_t)(hbase + m0 + ar) * HIDDEN + q0 * 8;
    }
    const __half* Bt = (G1 ? g_w1t : g_w2t) + (size_t)z * D_MODEL * HIDDEN;
    const __half* bsrc = Bt + (size_t)(n0 + ar) * KTOT + q0 * 8;

    float4 pa0, pa1, pb0, pb1;
    auto fetch = [&](int c) {
        const int k = c * BK;
        pa0 = *(const float4*)(asrc + k);
        pa1 = *(const float4*)(asrc + k + 8);
        pb0 = *(const float4*)(bsrc + k);
        pb1 = *(const float4*)(bsrc + k + 8);
    };
    auto stage_store = [&](int s) {
        __half* base = smbuf[s];
        *(float4*)(base + ar * A_LDH + q0 * 8)     = pa0;
        *(float4*)(base + ar * A_LDH + q0 * 8 + 8) = pa1;
        *(float4*)(base + A_STG_H + ar * B_LDH + q0 * 8)     = pb0;
        *(float4*)(base + A_STG_H + ar * B_LDH + q0 * 8 + 8) = pb1;
    };

    float acc[4][4][4];
    #pragma unroll
    for (int mt = 0; mt < 4; mt++)
        #pragma unroll
        for (int nt = 0; nt < 4; nt++)
            #pragma unroll
            for (int q = 0; q < 4; q++) acc[mt][nt][q] = 0.0f;

    fetch(0);
    stage_store(0);
    __syncthreads();

    #pragma unroll 1
    for (int c = 0; c < NC; c++) {
        const int s = c & 1;
        if (c + 1 < NC) fetch(c + 1);   // global->reg, overlapped with MMA below

        const uint32_t* Au = (const uint32_t*)smbuf[s];          // 20 u32 per row
        const uint32_t* Bu = Au + A_STG_H / 2;
        #pragma unroll
        for (int kk = 0; kk < 2; kk++) {
            uint32_t a[4][4], b[4][2];
            #pragma unroll
            for (int mt = 0; mt < 4; mt++) {
                const int r0 = wm + mt * 16 + fr;
                a[mt][0] = Au[r0 * 20 + kk * 8 + fc];
                a[mt][1] = Au[(r0 + 8) * 20 + kk * 8 + fc];
                a[mt][2] = Au[r0 * 20 + kk * 8 + fc + 4];
                a[mt][3] = Au[(r0 + 8) * 20 + kk * 8 + fc + 4];
            }
            #pragma unroll
            for (int nt = 0; nt < 4; nt++) {
                const int nr = wn + nt * 8 + fr;
                b[nt][0] = Bu[nr * 20 + kk * 8 + fc];
                b[nt][1] = Bu[nr * 20 + kk * 8 + fc + 4];
            }
            #pragma unroll
            for (int mt = 0; mt < 4; mt++)
                #pragma unroll
                for (int nt = 0; nt < 4; nt++)
                    mma_f16(acc[mt][nt], a[mt], b[nt]);
        }

        if (c + 1 < NC) {
            __syncthreads();            // all warps done reading stage s^1
            stage_store(s ^ 1);
            __syncthreads();            // stores visible before compute(c+1)
        }
    }

    // ---------------- epilogue (C frag: rows fr(+8), cols 2*fc(+1)) ----------------
    if (G1) {
        const float* bias = (z < NEXP) ? bias_r + (size_t)z * HIDDEN + n0
                                       : bias_s + (size_t)(z - NEXP) * HIDDEN + n0;
        #pragma unroll
        for (int mt = 0; mt < 4; mt++) {
            #pragma unroll
            for (int h2 = 0; h2 < 2; h2++) {
                const int mloc = wm + mt * 16 + fr + 8 * h2;
                if (m0 + mloc < cnt) {
                    __half* hrow = g_h + (size_t)(hbase + m0 + mloc) * HIDDEN + n0;
                    #pragma unroll
                    for (int nt = 0; nt < 4; nt++) {
                        const int col = wn + nt * 8 + 2 * fc;
                        const float v0 = gelu_exact(acc[mt][nt][2 * h2]     + bias[col]);
                        const float v1 = gelu_exact(acc[mt][nt][2 * h2 + 1] + bias[col + 1]);
                        *(__half2*)(hrow + col) = __floats2half2_rn(v0, v1);
                    }
                }
            }
        }
    } else {
        #pragma unroll
        for (int mt = 0; mt < 4; mt++) {
            #pragma unroll
            for (int h2 = 0; h2 < 2; h2++) {
                const int mloc = wm + mt * 16 + fr + 8 * h2;
                const int m = m0 + mloc;
                if (m < cnt) {
                    int t; float w;
                    if (z < NEXP) { t = g_slot_tok[z][m]; w = g_slot_w[z][m]; }
                    else          { t = m; w = 0.5f; }
                    float* orow = out + (size_t)t * D_MODEL + n0;
                    #pragma unroll
                    for (int nt = 0; nt < 4; nt++) {
                        const int col = wn + nt * 8 + 2 * fc;
                        atomicAdd(orow + col,     w * acc[mt][nt][2 * h2]);
                        atomicAdd(orow + col + 1, w * acc[mt][nt][2 * h2 + 1]);
                    }
                }
            }
        }
    }
}

// ---------------- launch ----------------
extern "C" void kernel_launch(void* const* d_in, const int* in_sizes, int n_in,
                              void* d_out, int out_size) {
    (void)in_sizes; (void)n_in; (void)out_size;
    const float* x   = (const float*)d_in[0];
    const float* rW  = (const float*)d_in[1];
    const float* rb  = (const float*)d_in[2];
    const float* W1  = (const float*)d_in[3];
    const float* b1  = (const float*)d_in[4];
    const float* W2  = (const float*)d_in[5];
    const float* b2  = (const float*)d_in[6];
    const float* sW1 = (const float*)d_in[7];
    const float* sb1 = (const float*)d_in[8];
    const float* sW2 = (const float*)d_in[9];
    const float* sb2 = (const float*)d_in[10];
    float* out = (float*)d_out;

    zero_counts_kernel<<<1, 32>>>();
    router_kernel<<<NTOK, 128>>>(x, rW, rb);
    offsets_kernel<<<1, 32>>>();
    conv_x_kernel<<<(NTOK * D_MODEL) / 1024, 256>>>(x);
    // W1 [z][D][H] -> [z][H][D] fp16 (dst resolved in device code)
    transp_kernel<<<dim3(HIDDEN / 32, D_MODEL / 32, NZ), dim3(32, 8)>>>(W1, sW1, 0, D_MODEL, HIDDEN);
    // GEMM1 is the 6th launch -> lands in the ncu capture slot (-s 5 -c 1)
    moe_mma<D_MODEL, true><<<dim3(CAP / BM, HIDDEN / BN, NZ), 256>>>(b1, sb1, nullptr);
    // W2 [z][H][D] -> [z][D][H] fp16
    transp_kernel<<<dim3(D_MODEL / 32, HIDDEN / 32, NZ), dim3(32, 8)>>>(W2, sW2, 1, HIDDEN, D_MODEL);
    init_out_kernel<<<(NTOK * D_MODEL) / 256, 256>>>(out, b2, sb2);
    moe_mma<HIDDEN, false><<<dim3(CAP / BM, D_MODEL / BN, NZ), 256>>>(nullptr, nullptr, out);
}

// round 9
// speedup vs baseline: 6.9537x; 1.6207x over previous
#include <cuda_runtime.h>
#include <cuda_fp16.h>
#include <cstdint>
#include <math.h>

#define D_MODEL 1024
#define HIDDEN  4096
#define NEXP    8
#define NSH     2
#define NTOK    4096
#define CAP     4096
#define NZ      (NEXP + NSH)
#define NSLOT   16384

// ---------------- device scratch (static; zero runtime allocation) ----------------
__device__ int   g_cnt[NEXP];
__device__ int   g_slot_tok[NEXP][CAP];
__device__ float g_slot_w[NEXP][CAP];
__device__ int   g_tok_e[NTOK][2];
__device__ float g_tok_w[NTOK][2];
__device__ int   g_grp_base[NZ];
__device__ int   g_grp_cnt[NZ];

__device__ __align__(16) __half g_xh[(size_t)NTOK * D_MODEL];            // x fp16
__device__ __align__(16) __half g_w1t[(size_t)NZ * HIDDEN * D_MODEL];    // W1^T fp16 [z][H][D]
__device__ __align__(16) __half g_w2t[(size_t)NZ * D_MODEL * HIDDEN];    // W2^T fp16 [z][D][H]
__device__ __align__(16) __half g_h[(size_t)NSLOT * HIDDEN];             // hidden acts fp16

__device__ __forceinline__ float gelu_exact(float v) {
    return 0.5f * v * (1.0f + erff(v * 0.70710678118654752440f));
}

// ---------------- PTX helpers ----------------
__device__ __forceinline__ uint32_t smem_u32(const void* p) {
    uint32_t a;
    asm("{ .reg .u64 t; cvta.to.shared.u64 t, %1; cvt.u32.u64 %0, t; }" : "=r"(a) : "l"(p));
    return a;
}
__device__ __forceinline__ void cp16(uint32_t dst, const void* src) {
    asm volatile("cp.async.cg.shared.global [%0], [%1], 16;\n" :: "r"(dst), "l"(src) : "memory");
}
#define CP_COMMIT() asm volatile("cp.async.commit_group;\n" ::: "memory")
template<int N> __device__ __forceinline__ void cp_wait() {
    asm volatile("cp.async.wait_group %0;\n" :: "n"(N) : "memory");
}
__device__ __forceinline__ void ldsm4(uint32_t& r0, uint32_t& r1, uint32_t& r2, uint32_t& r3,
                                      uint32_t addr) {
    asm volatile("ldmatrix.sync.aligned.m8n8.x4.shared.b16 {%0,%1,%2,%3}, [%4];"
                 : "=r"(r0), "=r"(r1), "=r"(r2), "=r"(r3) : "r"(addr));
}
__device__ __forceinline__ void mma_f16(float* d, const uint32_t* a, const uint32_t* b) {
    asm volatile(
        "mma.sync.aligned.m16n8k16.row.col.f32.f16.f16.f32 "
        "{%0,%1,%2,%3}, {%4,%5,%6,%7}, {%8,%9}, {%0,%1,%2,%3};"
        : "+f"(d[0]), "+f"(d[1]), "+f"(d[2]), "+f"(d[3])
        : "r"(a[0]), "r"(a[1]), "r"(a[2]), "r"(a[3]), "r"(b[0]), "r"(b[1]));
}

// ---------------- small kernels (proven) ----------------
__global__ void zero_counts_kernel() {
    if (threadIdx.x < NEXP) g_cnt[threadIdx.x] = 0;
}

__global__ void router_kernel(const float* __restrict__ x,
                              const float* __restrict__ rW,
                              const float* __restrict__ rb) {
    const int t = blockIdx.x, tid = threadIdx.x;
    __shared__ float sg[128][NEXP];
    float acc[NEXP];
    #pragma unroll
    for (int e = 0; e < NEXP; e++) acc[e] = 0.0f;
    const float* xr = x + (size_t)t * D_MODEL;
    for (int d = tid; d < D_MODEL; d += 128) {
        const float xv = xr[d];
        const float* r = rW + (size_t)d * NEXP;
        #pragma unroll
        for (int e = 0; e < NEXP; e++) acc[e] += xv * r[e];
    }
    #pragma unroll
    for (int e = 0; e < NEXP; e++) sg[tid][e] = acc[e];
    __syncthreads();
    if (tid < NEXP) {
        float s = rb[tid];
        for (int i = 0; i < 128; i++) s += sg[i][tid];
        sg[0][tid] = s;
    }
    __syncthreads();
    if (tid == 0) {
        float g[NEXP];
        #pragma unroll
        for (int e = 0; e < NEXP; e++) g[e] = sg[0][e];
        int e0 = 0;
        #pragma unroll
        for (int e = 1; e < NEXP; e++) if (g[e] > g[e0]) e0 = e;
        int e1 = (e0 == 0) ? 1 : 0;
        #pragma unroll
        for (int e = 0; e < NEXP; e++) if (e != e0 && g[e] > g[e1]) e1 = e;
        const float p1 = expf(g[e1] - g[e0]);
        const float inv = 1.0f / (1.0f + p1);
        const float w0 = inv, w1 = p1 * inv;
        g_tok_e[t][0] = e0; g_tok_e[t][1] = e1;
        g_tok_w[t][0] = w0; g_tok_w[t][1] = w1;
        int p = atomicAdd(&g_cnt[e0], 1);
        g_slot_tok[e0][p] = t; g_slot_w[e0][p] = w0;
        p = atomicAdd(&g_cnt[e1], 1);
        g_slot_tok[e1][p] = t; g_slot_w[e1][p] = w1;
    }
}

__global__ void offsets_kernel() {
    if (threadIdx.x == 0) {
        int acc = 0;
        for (int e = 0; e < NEXP; e++) { g_grp_base[e] = acc; g_grp_cnt[e] = g_cnt[e]; acc += g_cnt[e]; }
        for (int s = 0; s < NSH; s++)  { g_grp_base[NEXP + s] = 8192 + s * NTOK; g_grp_cnt[NEXP + s] = NTOK; }
    }
}

__global__ void init_out_kernel(float* __restrict__ out,
                                const float* __restrict__ b2,
                                const float* __restrict__ sb2) {
    const int idx = blockIdx.x * 256 + threadIdx.x;
    if (idx >= NTOK * D_MODEL) return;
    const int t = idx >> 10, d = idx & 1023;
    float v = 0.5f * (sb2[d] + sb2[D_MODEL + d]);
    v += g_tok_w[t][0] * b2[(size_t)g_tok_e[t][0] * D_MODEL + d];
    v += g_tok_w[t][1] * b2[(size_t)g_tok_e[t][1] * D_MODEL + d];
    out[idx] = v;
}

__global__ void conv_x_kernel(const float* __restrict__ x) {
    const int i = (blockIdx.x * 256 + threadIdx.x) * 4;
    const float4 v = *(const float4*)(x + i);
    *(__half2*)(g_xh + i)     = __floats2half2_rn(v.x, v.y);
    *(__half2*)(g_xh + i + 2) = __floats2half2_rn(v.z, v.w);
}

// [z][R][C] fp32 -> [z][C][R] fp16. dst resolved in DEVICE code (host-passed
// __device__ symbol was the R3/R5/R6/R7 stream-poison bug).
__global__ void transp_kernel(const float* __restrict__ srcR, const float* __restrict__ srcS,
                              int which, int R, int C) {
    __half* __restrict__ dst0 = which ? g_w2t : g_w1t;
    const int z = blockIdx.z;
    const float* src = (z < NEXP) ? srcR + (size_t)z * R * C : srcS + (size_t)(z - NEXP) * R * C;
    __half* d = dst0 + (size_t)z * R * C;
    __shared__ float tile[32][33];
    const int c0 = blockIdx.x * 32, r0 = blockIdx.y * 32;
    const int tx = threadIdx.x, ty = threadIdx.y;
    #pragma unroll
    for (int q = 0; q < 4; q++)
        tile[ty + 8 * q][tx] = src[(size_t)(r0 + ty + 8 * q) * C + c0 + tx];
    __syncthreads();
    #pragma unroll
    for (int q = 0; q < 4; q++)
        d[(size_t)(c0 + ty + 8 * q) * R + r0 + tx] = __float2half_rn(tile[tx][ty + 8 * q]);
}

// ---------------- fp16 mma grouped GEMM: cp.async 3-stage + ldmatrix ----------------
// CTA 128x128, BK=32 halfs (64B rows), XOR-swizzled smem, one syncthreads/chunk.
#define BM 128
#define BN 128
#define BK 32
#define STAGE_B 16384           // 8KB A + 8KB B per stage; 3 stages = 48KB static

__device__ __forceinline__ uint32_t swz(int row, int q) {
    return (uint32_t)(row * 64 + ((q ^ ((row >> 1) & 3)) << 4));
}

template<int KTOT, bool G1>
__global__ __launch_bounds__(256, 2) void moe_mma(
    const float* __restrict__ bias_r, const float* __restrict__ bias_s,
    float* __restrict__ out)
{
    constexpr int NC = KTOT / BK;
    const int z   = blockIdx.z;
    const int cnt = g_grp_cnt[z];
    const int m0  = blockIdx.x * BM;
    if (m0 >= cnt) return;
    const int n0    = blockIdx.y * BN;
    const int hbase = g_grp_base[z];

    __shared__ __align__(1024) uint8_t smbuf[3 * STAGE_B];
    const uint32_t sb = smem_u32(smbuf);

    const int tid = threadIdx.x, lane = tid & 31, wid = tid >> 5;
    const int wm = (wid & 1) * 64, wn = (wid >> 1) * 32;

    // ---- loader plan: thread -> rows (lr, lr+64), one 16B quad lq ----
    const int lr = tid >> 2, lq = tid & 3;
    const __half* asrc0;
    const __half* asrc1;
    if (G1) {
        int t0, t1;
        if (z < NEXP) {
            const int i0 = m0 + lr, i1 = m0 + lr + 64;
            t0 = g_slot_tok[z][i0 < cnt ? i0 : cnt - 1];
            t1 = g_slot_tok[z][i1 < cnt ? i1 : cnt - 1];
        } else { t0 = m0 + lr; t1 = m0 + lr + 64; }
        asrc0 = g_xh + (size_t)t0 * D_MODEL + lq * 8;
        asrc1 = g_xh + (size_t)t1 * D_MODEL + lq * 8;
    } else {
        asrc0 = g_h + (size_t)(hbase + m0 + lr) * HIDDEN + lq * 8;
        asrc1 = g_h + (size_t)(hbase + m0 + lr + 64) * HIDDEN + lq * 8;
    }
    const __half* Bt = (G1 ? g_w1t : g_w2t) + (size_t)z * D_MODEL * HIDDEN;
    const __half* bsrc0 = Bt + (size_t)(n0 + lr) * KTOT + lq * 8;
    const __half* bsrc1 = Bt + (size_t)(n0 + lr + 64) * KTOT + lq * 8;

    const uint32_t dA0 = swz(lr, lq), dA1 = swz(lr + 64, lq);
    const uint32_t dB0 = 8192u + dA0, dB1 = 8192u + dA1;

    // ---- fragment lane constants ----
    const int g  = lane >> 3, rin = lane & 7;
    const int gl = g & 1, gh = g >> 1;
    uint32_t aRow[4]; int aF[4];
    #pragma unroll
    for (int mt = 0; mt < 4; mt++) {
        const int r = wm + mt * 16 + gl * 8 + rin;
        aRow[mt] = (uint32_t)(r * 64);
        aF[mt]   = (r >> 1) & 3;
    }
    uint32_t bRow[2]; int bF[2];
    #pragma unroll
    for (int p = 0; p < 2; p++) {
        const int r = wn + p * 16 + gh * 8 + rin;
        bRow[p] = 8192u + (uint32_t)(r * 64);
        bF[p]   = (r >> 1) & 3;
    }

    float acc[4][4][4];
    #pragma unroll
    for (int mt = 0; mt < 4; mt++)
        #pragma unroll
        for (int nt = 0; nt < 4; nt++)
            #pragma unroll
            for (int q = 0; q < 4; q++) acc[mt][nt][q] = 0.0f;

    auto load_chunk = [&](int c, int s) {
        const uint32_t st = sb + (uint32_t)s * STAGE_B;
        const int ko = c * BK;
        cp16(st + dA0, asrc0 + ko);
        cp16(st + dA1, asrc1 + ko);
        cp16(st + dB0, bsrc0 + ko);
        cp16(st + dB1, bsrc1 + ko);
        CP_COMMIT();
    };

    load_chunk(0, 0);
    load_chunk(1, 1);

    int s = 0, s2 = 2;   // s = stage of chunk c; s2 = stage for chunk c+2
    #pragma unroll 1
    for (int c = 0; c < NC; c++) {
        if (c + 1 < NC) cp_wait<1>(); else cp_wait<0>();
        __syncthreads();                       // also protects stage s2 (read in c-1)
        if (c + 2 < NC) load_chunk(c + 2, s2);

        const uint32_t st = sb + (uint32_t)s * STAGE_B;
        #pragma unroll
        for (int kk = 0; kk < 2; kk++) {
            uint32_t a[4][4], b[4][2];
            #pragma unroll
            for (int mt = 0; mt < 4; mt++)
                ldsm4(a[mt][0], a[mt][1], a[mt][2], a[mt][3],
                      st + aRow[mt] + (uint32_t)(((2 * kk + gh) ^ aF[mt]) << 4));
            {
                uint32_t r0, r1, r2, r3;
                ldsm4(r0, r1, r2, r3, st + bRow[0] + (uint32_t)(((2 * kk + gl) ^ bF[0]) << 4));
                b[0][0] = r0; b[0][1] = r1; b[1][0] = r2; b[1][1] = r3;
                ldsm4(r0, r1, r2, r3, st + bRow[1] + (uint32_t)(((2 * kk + gl) ^ bF[1]) << 4));
                b[2][0] = r0; b[2][1] = r1; b[3][0] = r2; b[3][1] = r3;
            }
            #pragma unroll
            for (int mt = 0; mt < 4; mt++)
                #pragma unroll
                for (int nt = 0; nt < 4; nt++)
                    mma_f16(acc[mt][nt], a[mt], b[nt]);
        }
        s = (s == 2) ? 0 : s + 1;
        s2 = (s2 == 2) ? 0 : s2 + 1;
    }

    // ---------------- epilogue (C frag: rows fr(+8), cols 2*fc(+1)) ----------------
    const int fr = lane >> 2, fc = lane & 3;
    if (G1) {
        const float* bias = (z < NEXP) ? bias_r + (size_t)z * HIDDEN + n0
                                       : bias_s + (size_t)(z - NEXP) * HIDDEN + n0;
        #pragma unroll
        for (int mt = 0; mt < 4; mt++) {
            #pragma unroll
            for (int h2 = 0; h2 < 2; h2++) {
                const int mloc = wm + mt * 16 + fr + 8 * h2;
                if (m0 + mloc < cnt) {
                    __half* hrow = g_h + (size_t)(hbase + m0 + mloc) * HIDDEN + n0;
                    #pragma unroll
                    for (int nt = 0; nt < 4; nt++) {
                        const int col = wn + nt * 8 + 2 * fc;
                        const float v0 = gelu_exact(acc[mt][nt][2 * h2]     + bias[col]);
                        const float v1 = gelu_exact(acc[mt][nt][2 * h2 + 1] + bias[col + 1]);
                        *(__half2*)(hrow + col) = __floats2half2_rn(v0, v1);
                    }
                }
            }
        }
    } else {
        #pragma unroll
        for (int mt = 0; mt < 4; mt++) {
            #pragma unroll
            for (int h2 = 0; h2 < 2; h2++) {
                const int mloc = wm + mt * 16 + fr + 8 * h2;
                const int m = m0 + mloc;
                if (m < cnt) {
                    int t; float w;
                    if (z < NEXP) { t = g_slot_tok[z][m]; w = g_slot_w[z][m]; }
                    else          { t = m; w = 0.5f; }
                    float* orow = out + (size_t)t * D_MODEL + n0;
                    #pragma unroll
                    for (int nt = 0; nt < 4; nt++) {
                        const int col = wn + nt * 8 + 2 * fc;
                        atomicAdd(orow + col,     w * acc[mt][nt][2 * h2]);
                        atomicAdd(orow + col + 1, w * acc[mt][nt][2 * h2 + 1]);
                    }
                }
            }
        }
    }
}

// ---------------- launch ----------------
extern "C" void kernel_launch(void* const* d_in, const int* in_sizes, int n_in,
                              void* d_out, int out_size) {
    (void)in_sizes; (void)n_in; (void)out_size;
    const float* x   = (const float*)d_in[0];
    const float* rW  = (const float*)d_in[1];
    const float* rb  = (const float*)d_in[2];
    const float* W1  = (const float*)d_in[3];
    const float* b1  = (const float*)d_in[4];
    const float* W2  = (const float*)d_in[5];
    const float* b2  = (const float*)d_in[6];
    const float* sW1 = (const float*)d_in[7];
    const float* sb1 = (const float*)d_in[8];
    const float* sW2 = (const float*)d_in[9];
    const float* sb2 = (const float*)d_in[10];
    float* out = (float*)d_out;

    zero_counts_kernel<<<1, 32>>>();
    router_kernel<<<NTOK, 128>>>(x, rW, rb);
    offsets_kernel<<<1, 32>>>();
    conv_x_kernel<<<(NTOK * D_MODEL) / 1024, 256>>>(x);
    // W1 [z][D][H] -> [z][H][D] fp16
    transp_kernel<<<dim3(HIDDEN / 32, D_MODEL / 32, NZ), dim3(32, 8)>>>(W1, sW1, 0, D_MODEL, HIDDEN);
    // GEMM1 is the 6th launch -> lands in the ncu capture slot (-s 5 -c 1)
    moe_mma<D_MODEL, true><<<dim3(CAP / BM, HIDDEN / BN, NZ), 256>>>(b1, sb1, nullptr);
    // W2 [z][H][D] -> [z][D][H] fp16
    transp_kernel<<<dim3(D_MODEL / 32, HIDDEN / 32, NZ), dim3(32, 8)>>>(W2, sW2, 1, HIDDEN, D_MODEL);
    init_out_kernel<<<(NTOK * D_MODEL) / 256, 256>>>(out, b2, sb2);
    moe_mma<HIDDEN, false><<<dim3(CAP / BM, D_MODEL / BN, NZ), 256>>>(nullptr, nullptr, out);
}